// round 12
// baseline (speedup 1.0000x reference)
#include <cuda_runtime.h>
#include <cuda_fp16.h>
#include <math.h>
#include <stdint.h>

#define NB 128
#define TT 2000
#define LL 250
#define HH 512
#define KK 128
#define VV 128
#define AA 64
#define NBLK 256
#define NTHR 512

__device__ __align__(16) __half g_kb[(size_t)NB * TT * 128];
__device__ __align__(16) __half g_vb[(size_t)NB * TT * 128];
__device__ __align__(16) __half g_W1p[2048 * 640];
__device__ __align__(16) __half g_W2p[512 * 640];
__device__ __align__(16) __half g_x1[2][640 * 128];   // rows: 0-127 ctx, 128-639 h1
__device__ __align__(16) __half g_x2[2][640 * 128];   // rows: 0-511 h1, 512-639 h2
__device__ float g_h2N[128 * 128];
__device__ float g_PbT[2048 * 64];
__device__ float g_c1[512 * 128], g_c2[128 * 128];
__device__ float g_ps[NB * NBLK];
__device__ float g_pacc[(size_t)NB * NBLK * VV];
__device__ int   g_acnt[NB];
__device__ int   g_prefix[NB + 1];
__device__ int   g_bfirst[NB], g_blast[NB], g_bcnt[NB];
__device__ unsigned g_gen;
__device__ unsigned g_cgrp[16 * 32];     // padded group counters (128B apart)
__device__ unsigned g_croot;

struct SCt {
    float h2s[128];
    float wacc[16][128];
    float ctxs[128];
    float wsum[16];
    int   flag;
};

#define OFF_W1 0
#define OFF_W2 21248
#define OFF_XS 42496
#define OFF_U  77312
#define SMEM_TOTAL 87552
#define WST 664
#define XST 136
#define XBUF (64 * XST)

__device__ __forceinline__ float sigf(float x) { return 1.0f / (1.0f + __expf(-x)); }
__device__ __forceinline__ uint32_t cvta_s(const void* p) { return (uint32_t)__cvta_generic_to_shared(p); }
__device__ __forceinline__ void ldsm_x4(uint32_t& a0, uint32_t& a1, uint32_t& a2, uint32_t& a3, uint32_t a) {
    asm volatile("ldmatrix.sync.aligned.m8n8.x4.shared.b16 {%0,%1,%2,%3},[%4];"
        : "=r"(a0), "=r"(a1), "=r"(a2), "=r"(a3) : "r"(a));
}
__device__ __forceinline__ void ldsm_x2t(uint32_t& b0, uint32_t& b1, uint32_t a) {
    asm volatile("ldmatrix.sync.aligned.m8n8.x2.trans.shared.b16 {%0,%1},[%2];"
        : "=r"(b0), "=r"(b1) : "r"(a));
}
__device__ __forceinline__ void mma16816(float& d0, float& d1, float& d2, float& d3,
    uint32_t a0, uint32_t a1, uint32_t a2, uint32_t a3, uint32_t b0, uint32_t b1) {
    asm volatile("mma.sync.aligned.m16n8k16.row.col.f32.f16.f16.f32 "
        "{%0,%1,%2,%3},{%4,%5,%6,%7},{%8,%9},{%0,%1,%2,%3};"
        : "+f"(d0), "+f"(d1), "+f"(d2), "+f"(d3)
        : "r"(a0), "r"(a1), "r"(a2), "r"(a3), "r"(b0), "r"(b1));
}

// tree barrier: 16 groups x 16 blocks, padded counters -> no same-address pileup
__device__ __forceinline__ void gbar() {
    __syncthreads();
    __threadfence();
    if (threadIdx.x == 0) {
        unsigned my = *(volatile unsigned*)&g_gen;
        unsigned o = atomicAdd(&g_cgrp[(blockIdx.x >> 4) << 5], 1u);
        if (o == 15u) {
            unsigned r = atomicAdd(&g_croot, 1u);
            if (r == 15u) {
                g_croot = 0u;
#pragma unroll
                for (int i = 0; i < 16; i++) g_cgrp[i << 5] = 0u;
                __threadfence();
                atomicAdd(&g_gen, 1u);
            }
        }
        while (*(volatile unsigned*)&g_gen == my) { __nanosleep(32); }
        __threadfence();
    }
    __syncthreads();
}

// ---- launch 1: init state + meta ----
__global__ void setup_a(const float* __restrict__ values, const int* __restrict__ lens) {
    if (blockIdx.x == 0) {
        __shared__ int pre[NB + 1];
        if (threadIdx.x == 0) {
            int s = 0;
            for (int n = 0; n < NB; n++) { pre[n] = s; s += lens[n]; }
            pre[NB] = s;
            for (int i = 0; i <= NB; i++) g_prefix[i] = pre[i];
            for (int i = 0; i < 16; i++) g_cgrp[i << 5] = 0u;
            g_croot = 0u; g_gen = 0u;
        }
        __syncthreads();
        int n = threadIdx.x;
        if (n < NB) {
            long long W = pre[NB];
            int Pn = pre[n], Pn1 = pre[n + 1], bf = 0, bl = 0, cnt = 0;
            for (int b = 0; b < NBLK; b++) {
                int r0 = (int)((long long)b * W / NBLK);
                int r1 = (int)((long long)(b + 1) * W / NBLK);
                if (max(r0, Pn) < min(r1, Pn1)) { if (cnt == 0) bf = b; bl = b; cnt++; }
            }
            g_bfirst[n] = bf; g_blast[n] = bl; g_bcnt[n] = cnt;
        }
        return;
    }
    int i = (blockIdx.x - 1) * 256 + threadIdx.x;
    if (i < 512 * 128) g_c1[i] = 0.0f;
    if (i < 128 * 128) { g_c2[i] = 0.0f; g_x2[1][512 * 128 + i] = __float2half(0.0f); }
    if (i < 640 * 128) {
        int k = i >> 7, n = i & 127;
        g_x1[0][i] = (k < 128) ? __float2half(values[n * 128 + k]) : __float2half(0.0f);
    }
    if (i < NB) g_acnt[i] = 0;
}

// ---- launch 2: K/V transpose to [n][t][f] fp16 ----
__global__ void convkv_kernel(const float* __restrict__ key, const float* __restrict__ val) {
    int rid = blockIdx.x * 8 + (threadIdx.x >> 5);
    int lane = threadIdx.x & 31;
    if (rid < TT * NB) {
        int t = rid >> 7, n = rid & 127;
        float4 kv = *(const float4*)(key + ((size_t)rid << 7) + (lane << 2));
        float4 vv = *(const float4*)(val + ((size_t)rid << 7) + (lane << 2));
        size_t dst = ((size_t)n * TT + t) * 128 + (lane << 2);
        ((__half2*)(g_kb + dst))[0] = __floats2half2_rn(kv.x, kv.y);
        ((__half2*)(g_kb + dst))[1] = __floats2half2_rn(kv.z, kv.w);
        ((__half2*)(g_vb + dst))[0] = __floats2half2_rn(vv.x, vv.y);
        ((__half2*)(g_vb + dst))[1] = __floats2half2_rn(vv.z, vv.w);
    }
}

// ---- launch 3: weight permute/convert + PbT ----
__global__ void setup_b(const float* __restrict__ W_ih1, const float* __restrict__ W_hh1,
                        const float* __restrict__ W_ih2, const float* __restrict__ W_hh2,
                        const float* __restrict__ emb,
                        const float* __restrict__ b_ih1, const float* __restrict__ b_hh1) {
    int idx = blockIdx.x;    // 2624 blocks
    if (idx < 2048) {
        int ct = idx >> 4, r = idx & 15;
        int ca = ((r & 3) << 9) + ct * 4 + (r >> 2);
        for (int k = threadIdx.x; k < 640; k += 256) {
            float v = (k < 128) ? W_ih1[(size_t)ca * 640 + 512 + k]
                                : W_hh1[(size_t)ca * 512 + (k - 128)];
            g_W1p[(size_t)idx * 640 + k] = __float2half(v);
        }
    } else if (idx < 2560) {
        int i2 = idx - 2048, ct = i2 >> 4, r = i2 & 15;
        int cb = ((r & 3) << 7) + ct * 4 + (r >> 2);
        for (int k = threadIdx.x; k < 640; k += 256) {
            float v = (k < 512) ? W_ih2[(size_t)cb * 512 + k]
                                : W_hh2[(size_t)cb * 128 + (k - 512)];
            g_W2p[(size_t)i2 * 640 + k] = __float2half(v);
        }
    } else {
        const int ca = (idx - 2560) * 32 + (threadIdx.x & 31);
        const int rg = threadIdx.x >> 5;
        float acc[8];
#pragma unroll
        for (int i = 0; i < 8; i++) acc[i] = 0.0f;
        for (int k = 0; k < HH; k++) {
            float w = W_ih1[(size_t)ca * 640 + k];
#pragma unroll
            for (int i = 0; i < 8; i++) acc[i] = fmaf(emb[(size_t)(rg * 8 + i) * HH + k], w, acc[i]);
        }
        float bb = b_ih1[ca] + b_hh1[ca];
#pragma unroll
        for (int i = 0; i < 8; i++) g_PbT[(size_t)ca * 64 + rg * 8 + i] = acc[i] + bb;
    }
}

// ---- launch 4: persistent decoder ----
__global__ __launch_bounds__(NTHR, 2) void decoder_main(
    const int* __restrict__ text,
    const float* __restrict__ b_ih2, const float* __restrict__ b_hh2,
    const float* __restrict__ W_mos, const float* __restrict__ b_mos,
    float* __restrict__ out)
{
    extern __shared__ __align__(16) char sm[];
    __half* W1s = (__half*)(sm + OFF_W1);
    __half* W2s = (__half*)(sm + OFF_W2);
    __half* Xs  = (__half*)(sm + OFF_XS);
    float*  sgA = (float*)(sm + OFF_U);
    SCt&    sc  = *(SCt*)(sm + OFF_U);
    __shared__ int toks[64];
    __shared__ int s_pre[NB + 1];

    const int blk = blockIdx.x, tid = threadIdx.x;
    const int w = tid >> 5, lane = tid & 31;
    const uint32_t uW1 = cvta_s(W1s), uW2 = cvta_s(W2s), uXs = cvta_s(Xs);

    {
        const int ct = blk >> 1;
        for (int s = tid; s < 1280; s += NTHR) {
            int r = s / 80, seg = s - r * 80;
            *(uint4*)&W1s[r * WST + seg * 8] = *(const uint4*)&g_W1p[(size_t)(ct * 16 + r) * 640 + seg * 8];
        }
        if (blk < 64) {
            const int bt = blk >> 1;
            for (int s = tid; s < 1280; s += NTHR) {
                int r = s / 80, seg = s - r * 80;
                *(uint4*)&W2s[r * WST + seg * 8] = *(const uint4*)&g_W2p[(size_t)(bt * 16 + r) * 640 + seg * 8];
            }
        }
        for (int i = tid; i <= NB; i += NTHR) s_pre[i] = g_prefix[i];
    }
    __syncthreads();

    const long long Wtot = s_pre[NB];
    const int r0 = (int)((long long)blk * Wtot / NBLK);
    const int r1 = (int)((long long)(blk + 1) * Wtot / NBLK);
    int n0 = 0;
    for (int n = 1; n < NB; n++) { if (s_pre[n] <= r0) n0 = n; else break; }

    const int grp = tid >> 8;
    const int tg  = tid & 255;
    const int ww  = (tid >> 5) & 7;
    const int sr  = tg >> 2, sseg = tg & 3;
    __half* Xg = Xs + grp * XBUF;
    const uint32_t uXg = uXs + grp * XBUF * 2;
    const uint32_t aOfs = (uint32_t)(lane & 15) * WST + ((lane >> 4) << 3);
    const uint32_t stA = (uint32_t)(sr * XST + sseg * 8);

    for (int l = 0; l < LL; l++) {
        const int q = l & 1;

        // ===== phase A: LSTM1 gates, split-K HMMA =====
        {
            const int ct = blk >> 1, nh = blk & 1;
            if (tid < 64) toks[tid] = text[((nh << 6) + tid) * LL + l];
            const __half* x1p = g_x1[q] + (nh << 6);
            float d0 = 0.f, d1 = 0.f, d2 = 0.f, d3 = 0.f;
            uint4 pf0, pf1;
            {
                const __half* s = x1p + (((grp * 5) * 64 + sr) << 7);
                pf0 = *(const uint4*)(s + sseg * 8);
                pf1 = *(const uint4*)(s + 32 + sseg * 8);
            }
#pragma unroll 1
            for (int i = 0; i < 5; i++) {
                __syncthreads();
                *(uint4*)&Xg[stA]      = pf0;
                *(uint4*)&Xg[stA + 32] = pf1;
                __syncthreads();
                if (i < 4) {
                    const __half* s = x1p + (((grp * 5 + i + 1) * 64 + sr) << 7);
                    pf0 = *(const uint4*)(s + sseg * 8);
                    pf1 = *(const uint4*)(s + 32 + sseg * 8);
                }
                const int ch = grp * 5 + i;
#pragma unroll
                for (int ks = 0; ks < 4; ks++) {
                    uint32_t a0, a1, a2, a3, b0, b1;
                    ldsm_x4(a0, a1, a2, a3, uW1 + (aOfs + (ch << 6) + (ks << 4)) * 2);
                    ldsm_x2t(b0, b1, uXg + ((((ks << 4) + (lane & 15)) * XST) + (ww << 3)) * 2);
                    mma16816(d0, d1, d2, d3, a0, a1, a2, a3, b0, b1);
                }
            }
            __syncthreads();
            {
                int r = lane >> 2, c = (ww << 3) + ((lane & 3) << 1);
                float* dst = sgA + grp * 1088;
                dst[r * 68 + c] = d0;       dst[r * 68 + c + 1] = d1;
                dst[(r + 8) * 68 + c] = d2; dst[(r + 8) * 68 + c + 1] = d3;
            }
            __syncthreads();
            if (tid < 256) {
                const int u = tid >> 6, an = tid & 63, n = (nh << 6) + an;
                const int tok = toks[an];
                const int base = ct * 4 + u;
                float gi = sgA[(4 * u + 0) * 68 + an] + sgA[1088 + (4 * u + 0) * 68 + an] + g_PbT[(size_t)(base) * 64 + tok];
                float gf = sgA[(4 * u + 1) * 68 + an] + sgA[1088 + (4 * u + 1) * 68 + an] + g_PbT[(size_t)(512 + base) * 64 + tok];
                float gg = sgA[(4 * u + 2) * 68 + an] + sgA[1088 + (4 * u + 2) * 68 + an] + g_PbT[(size_t)(1024 + base) * 64 + tok];
                float go = sgA[(4 * u + 3) * 68 + an] + sgA[1088 + (4 * u + 3) * 68 + an] + g_PbT[(size_t)(1536 + base) * 64 + tok];
                const int ci = (base << 7) + n;
                float cn = sigf(gf) * g_c1[ci] + sigf(gi) * tanhf(gg);
                g_c1[ci] = cn;
                __half hval = __float2half(sigf(go) * tanhf(cn));
                g_x1[q ^ 1][((128 + base) << 7) + n] = hval;
                g_x2[q ^ 1][(base << 7) + n] = hval;
            }
        }
        gbar();

        // ===== phase B: LSTM2 gates (64 blocks), split-K HMMA =====
        if (blk < 64) {
            const int bt = blk >> 1, nh = blk & 1;
            const __half* x2p = g_x2[q ^ 1] + (nh << 6);
            float d0 = 0.f, d1 = 0.f, d2 = 0.f, d3 = 0.f;
            uint4 pf0, pf1;
            {
                const __half* s = x2p + (((grp * 5) * 64 + sr) << 7);
                pf0 = *(const uint4*)(s + sseg * 8);
                pf1 = *(const uint4*)(s + 32 + sseg * 8);
            }
#pragma unroll 1
            for (int i = 0; i < 5; i++) {
                __syncthreads();
                *(uint4*)&Xg[stA]      = pf0;
                *(uint4*)&Xg[stA + 32] = pf1;
                __syncthreads();
                if (i < 4) {
                    const __half* s = x2p + (((grp * 5 + i + 1) * 64 + sr) << 7);
                    pf0 = *(const uint4*)(s + sseg * 8);
                    pf1 = *(const uint4*)(s + 32 + sseg * 8);
                }
                const int ch = grp * 5 + i;
#pragma unroll
                for (int ks = 0; ks < 4; ks++) {
                    uint32_t a0, a1, a2, a3, b0, b1;
                    ldsm_x4(a0, a1, a2, a3, uW2 + (aOfs + (ch << 6) + (ks << 4)) * 2);
                    ldsm_x2t(b0, b1, uXg + ((((ks << 4) + (lane & 15)) * XST) + (ww << 3)) * 2);
                    mma16816(d0, d1, d2, d3, a0, a1, a2, a3, b0, b1);
                }
            }
            __syncthreads();
            {
                int r = lane >> 2, c = (ww << 3) + ((lane & 3) << 1);
                float* dst = sgA + grp * 1088;
                dst[r * 68 + c] = d0;       dst[r * 68 + c + 1] = d1;
                dst[(r + 8) * 68 + c] = d2; dst[(r + 8) * 68 + c + 1] = d3;
            }
            __syncthreads();
            if (tid < 256) {
                const int u = tid >> 6, an = tid & 63, n = (nh << 6) + an;
                const int base = bt * 4 + u;
                float gi = sgA[(4 * u + 0) * 68 + an] + sgA[1088 + (4 * u + 0) * 68 + an] + b_ih2[base]       + b_hh2[base];
                float gf = sgA[(4 * u + 1) * 68 + an] + sgA[1088 + (4 * u + 1) * 68 + an] + b_ih2[128 + base] + b_hh2[128 + base];
                float gg = sgA[(4 * u + 2) * 68 + an] + sgA[1088 + (4 * u + 2) * 68 + an] + b_ih2[256 + base] + b_hh2[256 + base];
                float go = sgA[(4 * u + 3) * 68 + an] + sgA[1088 + (4 * u + 3) * 68 + an] + b_ih2[384 + base] + b_hh2[384 + base];
                const int ci = (base << 7) + n;
                float cn = sigf(gf) * g_c2[ci] + sigf(gi) * tanhf(gg);
                g_c2[ci] = cn;
                float h2v = sigf(go) * tanhf(cn);
                g_h2N[(n << 7) + base] = h2v;
                g_x2[q][((512 + base) << 7) + n] = __float2half(h2v);
            }
        }
        gbar();

        // ===== phase C: attention, constant-shift softmax (no serial chain) =====
        {
            for (int n = n0; n < NB && s_pre[n] < r1; n++) {
                const int Pn = s_pre[n], Pn1 = s_pre[n + 1];
                const int tlo = max(r0, Pn) - Pn;
                const int thi = min(r1, Pn1) - Pn;
                if (thi <= tlo) continue;

                if (tid < KK) sc.h2s[tid] = __ldcg(&g_h2N[(n << 7) + tid]);
                __syncthreads();
                const float4 hv = *(const float4*)&sc.h2s[lane << 2];

                float ssum = 0.0f;
                float4 acc = make_float4(0.f, 0.f, 0.f, 0.f);
                const __half* kbase = g_kb + (size_t)n * TT * 128 + (lane << 2);
                const __half* vbase = g_vb + (size_t)n * TT * 128 + (lane << 2);

                int t = tlo + w;
                for (; t + 16 < thi; t += 32) {
                    const __half* kp = kbase + (size_t)t * 128;
                    const __half* vp = vbase + (size_t)t * 128;
                    uint2 kw0 = *(const uint2*)kp;
                    uint2 kw1 = *(const uint2*)(kp + 2048);
                    uint2 vw0 = *(const uint2*)vp;
                    uint2 vw1 = *(const uint2*)(vp + 2048);
                    float2 a0 = __half22float2(*(__half2*)&kw0.x);
                    float2 b0 = __half22float2(*(__half2*)&kw0.y);
                    float2 a1 = __half22float2(*(__half2*)&kw1.x);
                    float2 b1 = __half22float2(*(__half2*)&kw1.y);
                    float d0 = a0.x * hv.x + a0.y * hv.y + b0.x * hv.z + b0.y * hv.w;
                    float d1 = a1.x * hv.x + a1.y * hv.y + b1.x * hv.z + b1.y * hv.w;
#pragma unroll
                    for (int o = 16; o; o >>= 1) {
                        d0 += __shfl_xor_sync(0xffffffffu, d0, o);
                        d1 += __shfl_xor_sync(0xffffffffu, d1, o);
                    }
                    float p0 = __expf(d0 - 10.0f);
                    float p1 = __expf(d1 - 10.0f);
                    ssum += p0 + p1;
                    float2 va0 = __half22float2(*(__half2*)&vw0.x);
                    float2 vb0 = __half22float2(*(__half2*)&vw0.y);
                    float2 va1 = __half22float2(*(__half2*)&vw1.x);
                    float2 vb1 = __half22float2(*(__half2*)&vw1.y);
                    acc.x += p0 * va0.x + p1 * va1.x;
                    acc.y += p0 * va0.y + p1 * va1.y;
                    acc.z += p0 * vb0.x + p1 * vb1.x;
                    acc.w += p0 * vb0.y + p1 * vb1.y;
                }
                for (; t < thi; t += 16) {
                    const __half* kp = kbase + (size_t)t * 128;
                    const __half* vp = vbase + (size_t)t * 128;
                    uint2 kw = *(const uint2*)kp;
                    uint2 vw = *(const uint2*)vp;
                    float2 a0 = __half22float2(*(__half2*)&kw.x);
                    float2 b0 = __half22float2(*(__half2*)&kw.y);
                    float d = a0.x * hv.x + a0.y * hv.y + b0.x * hv.z + b0.y * hv.w;
#pragma unroll
                    for (int o = 16; o; o >>= 1) d += __shfl_xor_sync(0xffffffffu, d, o);
                    float pp = __expf(d - 10.0f);
                    ssum += pp;
                    float2 va = __half22float2(*(__half2*)&vw.x);
                    float2 vb = __half22float2(*(__half2*)&vw.y);
                    acc.x += pp * va.x;
                    acc.y += pp * va.y;
                    acc.z += pp * vb.x;
                    acc.w += pp * vb.y;
                }

                if (lane == 0) sc.wsum[w] = ssum;
                *(float4*)&sc.wacc[w][lane << 2] = acc;
                __syncthreads();

                const int cnt = g_bcnt[n];
                if (cnt == 1) {
                    // whole row local: combine + ctx + MoS without global round-trip
                    if (tid < VV) {
                        float S = 0.0f, C = 0.0f;
#pragma unroll
                        for (int w2 = 0; w2 < 16; w2++) { S += sc.wsum[w2]; C += sc.wacc[w2][tid]; }
                        float cv = C / S;
                        sc.ctxs[tid] = cv;
                        g_x1[q ^ 1][(tid << 7) + n] = __float2half(cv);
                    }
                    __syncthreads();
                    if (tid < AA) {
                        float a = b_mos[tid];
                        const float* wr = W_mos + (size_t)tid * (KK + VV);
#pragma unroll 4
                        for (int k = 0; k < KK; k++) a = fmaf(sc.h2s[k], wr[k], a);
#pragma unroll 4
                        for (int v = 0; v < VV; v++) a = fmaf(sc.ctxs[v], wr[KK + v], a);
                        out[((size_t)n * LL + l) * AA + tid] = a;
                    }
                    __syncthreads();
                    continue;
                }

                const int slot = blk - g_bfirst[n];
                if (tid < VV) {
                    float S = 0.0f, C = 0.0f;
#pragma unroll
                    for (int w2 = 0; w2 < 16; w2++) { S += sc.wsum[w2]; C += sc.wacc[w2][tid]; }
                    g_pacc[((size_t)n * NBLK + slot) * VV + tid] = C;
                    if (tid == 0) g_ps[n * NBLK + slot] = S;
                    __threadfence();
                }
                __syncthreads();
                if (tid == 0) {
                    int old = atomicAdd(&g_acnt[n], 1);
                    __threadfence();
                    sc.flag = (old == cnt - 1);
                }
                __syncthreads();
                if (sc.flag) {
                    if (tid < VV) {
                        float S = 0.0f, C = 0.0f;
                        for (int s2 = 0; s2 < cnt; s2++) {
                            S += __ldcg(&g_ps[n * NBLK + s2]);
                            C += __ldcg(&g_pacc[((size_t)n * NBLK + s2) * VV + tid]);
                        }
                        float cv = C / S;
                        sc.ctxs[tid] = cv;
                        g_x1[q ^ 1][(tid << 7) + n] = __float2half(cv);
                    }
                    if (tid == 0) g_acnt[n] = 0;
                    __syncthreads();
                    if (tid < AA) {
                        float a = b_mos[tid];
                        const float* wr = W_mos + (size_t)tid * (KK + VV);
#pragma unroll 4
                        for (int k = 0; k < KK; k++) a = fmaf(sc.h2s[k], wr[k], a);
#pragma unroll 4
                        for (int v = 0; v < VV; v++) a = fmaf(sc.ctxs[v], wr[KK + v], a);
                        out[((size_t)n * LL + l) * AA + tid] = a;
                    }
                }
                __syncthreads();
            }
        }
        gbar();
    }
}

extern "C" void kernel_launch(void* const* d_in, const int* in_sizes, int n_in,
                              void* d_out, int out_size) {
    (void)in_sizes; (void)n_in; (void)out_size;
    const float* key    = (const float*)d_in[0];
    const float* values = (const float*)d_in[1];
    const int*   lens   = (const int*)  d_in[2];
    const int*   text   = (const int*)  d_in[3];
    const float* emb    = (const float*)d_in[4];
    const float* W_ih1  = (const float*)d_in[5];
    const float* W_hh1  = (const float*)d_in[6];
    const float* b_ih1  = (const float*)d_in[7];
    const float* b_hh1  = (const float*)d_in[8];
    const float* W_ih2  = (const float*)d_in[9];
    const float* W_hh2  = (const float*)d_in[10];
    const float* b_ih2  = (const float*)d_in[11];
    const float* b_hh2  = (const float*)d_in[12];
    const float* W_mos  = (const float*)d_in[13];
    const float* b_mos  = (const float*)d_in[14];
    float* out = (float*)d_out;

    static int s_attr = 0;
    if (!s_attr) {
        cudaFuncSetAttribute(decoder_main, cudaFuncAttributeMaxDynamicSharedMemorySize, SMEM_TOTAL);
        s_attr = 1;
    }
    setup_a<<<513, 256>>>(values, lens);
    convkv_kernel<<<32000, 256>>>(key, values);
    setup_b<<<2624, 256>>>(W_ih1, W_hh1, W_ih2, W_hh2, emb, b_ih1, b_hh1);
    decoder_main<<<NBLK, NTHR, SMEM_TOTAL>>>(text, b_ih2, b_hh2, W_mos, b_mos, out);
}